// round 1
// baseline (speedup 1.0000x reference)
#include <cuda_runtime.h>
#include <math.h>

// Problem constants (fixed by setup_inputs)
#define Bb 4
#define Ss 128
#define Nn 512
#define Hh 64
#define Mm (Bb*Nn)          // 2048 heads
#define XSTR 65             // padded row stride for 64-wide tiles (conflict-free lane-strided reads)
#define SSTR 132            // padded row stride for 128-wide scores tile (16B-aligned float4 rows)
#define NTH 256

// Precomputed fused-projection operands
__device__ float g_G[Hh*Hh];   // scale * Wq^T Wk   [h1][h2]
__device__ float g_u[Hh];      // scale * Wq^T bk
__device__ float g_w[Hh];      // scale * Wk^T bq
__device__ float g_c0;         // scale * bq.bk

__global__ void precompute_k(const float* __restrict__ Wq, const float* __restrict__ bq,
                             const float* __restrict__ Wk, const float* __restrict__ bk) {
    int gid = blockIdx.x * blockDim.x + threadIdx.x;
    const float scale = 0.125f;  // 1/sqrt(64)
    if (gid < Hh * Hh) {
        int h1 = gid >> 6, h2 = gid & 63;
        float s = 0.f;
        #pragma unroll 8
        for (int o = 0; o < Hh; o++) s += Wq[o*Hh + h1] * Wk[o*Hh + h2];
        g_G[gid] = s * scale;
    }
    if (gid < Hh) {
        float s = 0.f, t = 0.f;
        #pragma unroll 8
        for (int o = 0; o < Hh; o++) { s += Wq[o*Hh + gid] * bk[o]; t += Wk[o*Hh + gid] * bq[o]; }
        g_u[gid] = s * scale;
        g_w[gid] = t * scale;
    }
    if (gid == 0) {
        float s = 0.f;
        for (int o = 0; o < Hh; o++) s += bq[o] * bk[o];
        g_c0 = s * scale;
    }
}

// Fused kernel: one CTA per head m = b*N + n.
//   P = X_traffic @ G            (128x64)
//   V = X_text @ Wv^T + bv       (128x64)
//   scores = P @ X_text^T + rb[s] + cb[t]    (128x128, pre-scaled)
//   per row: top-16 -> softmax -> attn out; sparse AV; residual + LayerNorm -> out
extern __shared__ float smf[];
__global__ void __launch_bounds__(NTH, 1)
fused_align_k(const float* __restrict__ traffic, const float* __restrict__ text,
              const float* __restrict__ Wv, const float* __restrict__ bv,
              const float* __restrict__ gamma, const float* __restrict__ beta,
              const int* __restrict__ topk_p,
              float* __restrict__ out_main, float* __restrict__ out_attn) {
    // shared layout
    float* xt_tr = smf;                         // 128*XSTR
    float* xt_tx = smf + 128*XSTR;              // 128*XSTR
    float* Pm    = smf + 2*128*XSTR;            // 128*XSTR
    float* vsm   = smf + 3*128*XSTR;            // 128*XSTR
    float* sc    = smf + 4*128*XSTR;            // 128*SSTR (scores; overlaps Gs/Wvt staging)
    float* Gs    = sc;                          // 4096 (dead before scores written)
    float* Wvt   = sc + 4096;                   // 4096 [h][c]
    float* tail  = smf + 4*128*XSTR + 128*SSTR;
    float* sg  = tail;        // gamma 64
    float* sb  = tail + 64;   // beta 64
    float* sbv = tail + 128;  // bv 64
    float* su  = tail + 192;  // u 64
    float* sw_ = tail + 256;  // w 64
    float* rb  = tail + 320;  // 128
    float* cb  = tail + 448;  // 128

    const int tid = threadIdx.x;
    const int lane = tid & 31;
    const int wrp = tid >> 5;
    const int m = blockIdx.x;
    const int b = m >> 9;       // N = 512
    const int n = m & (Nn - 1);

    const float* tr_base = traffic + ((size_t)b * Ss * Nn + n) * Hh; // row s at + s*Nn*Hh
    const float* tx_base = text    + ((size_t)b * Ss * Nn + n) * Hh;

    // ---- Stage 0: fill shared memory ----
    for (int i = tid; i < 4096; i += NTH) Gs[i] = g_G[i];
    for (int i = tid; i < 4096; i += NTH) {      // Wvt[h*64+c] = Wv[c*64+h]; conflict-free STS
        int c = i & 63, h = i >> 6;
        Wvt[i] = Wv[c * 64 + h];
    }
    for (int i = tid; i < 128 * 16; i += NTH) {
        int r = i >> 4, f = i & 15;
        float4 a = *(const float4*)(tr_base + (size_t)r * Nn * Hh + f * 4);
        float* d = xt_tr + r * XSTR + f * 4;
        d[0] = a.x; d[1] = a.y; d[2] = a.z; d[3] = a.w;
        float4 bx = *(const float4*)(tx_base + (size_t)r * Nn * Hh + f * 4);
        float* e = xt_tx + r * XSTR + f * 4;
        e[0] = bx.x; e[1] = bx.y; e[2] = bx.z; e[3] = bx.w;
    }
    if (tid < 64) {
        sg[tid] = gamma[tid]; sb[tid] = beta[tid]; sbv[tid] = bv[tid];
        su[tid] = g_u[tid];   sw_[tid] = g_w[tid];
    }
    __syncthreads();

    // ---- Stage 1: bias row/col terms + P GEMM + V GEMM ----
    if (tid < 128) {
        float s = g_c0;
        const float* xr = xt_tr + tid * XSTR;
        #pragma unroll 8
        for (int h = 0; h < 64; h++) s += xr[h] * su[h];
        rb[tid] = s;
    } else {
        int t2 = tid - 128;
        float s = 0.f;
        const float* xr = xt_tx + t2 * XSTR;
        #pragma unroll 8
        for (int h = 0; h < 64; h++) s += xr[h] * sw_[h];
        cb[t2] = s;
    }

    {
        const int c0 = wrp * 8;
        float accP[4][8], accV[4][8];
        #pragma unroll
        for (int i = 0; i < 4; i++)
            #pragma unroll
            for (int j = 0; j < 8; j++) { accP[i][j] = 0.f; accV[i][j] = sbv[c0 + j]; }
        #pragma unroll 4
        for (int h = 0; h < 64; h++) {
            float xtr[4], xtx[4];
            #pragma unroll
            for (int i = 0; i < 4; i++) {
                xtr[i] = xt_tr[(lane + 32*i) * XSTR + h];   // lane-stride-1: conflict-free
                xtx[i] = xt_tx[(lane + 32*i) * XSTR + h];
            }
            #pragma unroll
            for (int j = 0; j < 8; j++) {
                float gv = Gs[h * 64 + c0 + j];             // warp broadcast
                float wv = Wvt[h * 64 + c0 + j];
                #pragma unroll
                for (int i = 0; i < 4; i++) {
                    accP[i][j] += xtr[i] * gv;
                    accV[i][j] += xtx[i] * wv;
                }
            }
        }
        #pragma unroll
        for (int i = 0; i < 4; i++)
            #pragma unroll
            for (int j = 0; j < 8; j++) {
                Pm [(lane + 32*i) * XSTR + c0 + j] = accP[i][j];
                vsm[(lane + 32*i) * XSTR + c0 + j] = accV[i][j];
            }
    }
    __syncthreads();

    // ---- Stage 2: scores GEMM (writes over Gs/Wvt region) ----
    {
        const int t0 = wrp * 16;
        float cbl[16];
        #pragma unroll
        for (int j = 0; j < 16; j++) cbl[j] = cb[t0 + j];
        float acc[4][16];
        #pragma unroll
        for (int i = 0; i < 4; i++) {
            float r = rb[lane + 32*i];
            #pragma unroll
            for (int j = 0; j < 16; j++) acc[i][j] = r + cbl[j];
        }
        #pragma unroll 4
        for (int h = 0; h < 64; h++) {
            float pv[4];
            #pragma unroll
            for (int i = 0; i < 4; i++) pv[i] = Pm[(lane + 32*i) * XSTR + h];
            #pragma unroll
            for (int j = 0; j < 16; j++) {
                float xb = xt_tx[(t0 + j) * XSTR + h];      // warp broadcast
                #pragma unroll
                for (int i = 0; i < 4; i++) acc[i][j] += pv[i] * xb;
            }
        }
        #pragma unroll
        for (int i = 0; i < 4; i++)
            #pragma unroll
            for (int j = 0; j < 16; j++)
                sc[(lane + 32*i) * SSTR + t0 + j] = acc[i][j];
    }
    __syncthreads();

    // ---- Stage 3: per-row top-k + softmax + attn write + sparse AV + residual LN ----
    int kk = 16;
    if (topk_p) { kk = topk_p[0]; if (kk < 1) kk = 1; if (kk > 32) kk = 32; }

    float* attn_base = out_attn + (size_t)m * Ss * Ss;
    const int sbase = wrp * 16;
    const unsigned FULL = 0xffffffffu;

    for (int rr = 0; rr < 16; ++rr) {
        const int s = sbase + rr;
        float4 q4 = *(float4*)(sc + s * SSTR + lane * 4);
        const float o0 = q4.x, o1 = q4.y, o2 = q4.z, o3 = q4.w;
        float w0 = o0, w1 = o1, w2 = o2, w3 = o3;
        float maxv = 0.f, thr = 0.f, selv = 0.f;
        int seli = 0;

        for (int it = 0; it < kk; ++it) {
            float bvv = w0; int bj = 0;
            if (w1 > bvv) { bvv = w1; bj = 1; }
            if (w2 > bvv) { bvv = w2; bj = 2; }
            if (w3 > bvv) { bvv = w3; bj = 3; }
            int gi = lane * 4 + bj;
            #pragma unroll
            for (int off = 16; off > 0; off >>= 1) {
                float ov = __shfl_xor_sync(FULL, bvv, off);
                int   oi = __shfl_xor_sync(FULL, gi, off);
                if (ov > bvv || (ov == bvv && oi < gi)) { bvv = ov; gi = oi; }
            }
            if (it == 0) maxv = bvv;
            thr = bvv;
            if (lane == it) { selv = bvv; seli = gi; }
            if ((gi >> 2) == lane) {             // clear the winner in its owner lane
                int j = gi & 3;
                if (j == 0) w0 = -INFINITY;
                else if (j == 1) w1 = -INFINITY;
                else if (j == 2) w2 = -INFINITY;
                else w3 = -INFINITY;
            }
        }

        // softmax over selected (>= thr); unselected -> exactly 0
        float e0 = (o0 >= thr) ? __expf(o0 - maxv) : 0.f;
        float e1 = (o1 >= thr) ? __expf(o1 - maxv) : 0.f;
        float e2 = (o2 >= thr) ? __expf(o2 - maxv) : 0.f;
        float e3 = (o3 >= thr) ? __expf(o3 - maxv) : 0.f;
        float z = e0 + e1 + e2 + e3;
        #pragma unroll
        for (int off = 16; off > 0; off >>= 1) z += __shfl_xor_sync(FULL, z, off);
        float inv = 1.0f / z;

        float4 st; st.x = e0 * inv; st.y = e1 * inv; st.z = e2 * inv; st.w = e3 * inv;
        *(float4*)(attn_base + (size_t)s * Ss + lane * 4) = st;

        // sparse AV: lanes 0..kk-1 carry (p_i, idx_i)
        float p = (lane < kk) ? __expf(selv - maxv) * inv : 0.f;
        float a0 = 0.f, a1 = 0.f;
        for (int i2 = 0; i2 < kk; i2++) {
            float pi = __shfl_sync(FULL, p, i2);
            int   ti = __shfl_sync(FULL, seli, i2);
            const float* vr = vsm + ti * XSTR;
            a0 += pi * vr[lane];
            a1 += pi * vr[lane + 32];
        }

        // residual + LayerNorm over H=64 (2 elems/lane)
        float r0 = a0 + xt_tr[s * XSTR + lane];
        float r1 = a1 + xt_tr[s * XSTR + lane + 32];
        float sm1 = r0 + r1;
        #pragma unroll
        for (int off = 16; off > 0; off >>= 1) sm1 += __shfl_xor_sync(FULL, sm1, off);
        float mu = sm1 * (1.0f / 64.0f);
        float d0 = r0 - mu, d1 = r1 - mu;
        float sq = d0 * d0 + d1 * d1;
        #pragma unroll
        for (int off = 16; off > 0; off >>= 1) sq += __shfl_xor_sync(FULL, sq, off);
        float inv_sd = rsqrtf(sq * (1.0f / 64.0f) + 1e-5f);

        float* ob = out_main + (((size_t)(b * Ss + s)) * Nn + n) * Hh;
        ob[lane]      = d0 * inv_sd * sg[lane]      + sb[lane];
        ob[lane + 32] = d1 * inv_sd * sg[lane + 32] + sb[lane + 32];
    }
}

extern "C" void kernel_launch(void* const* d_in, const int* in_sizes, int n_in,
                              void* d_out, int out_size) {
    const float* traffic = (const float*)d_in[0];
    const float* text    = (const float*)d_in[1];
    const float* Wq      = (const float*)d_in[2];
    const float* bq      = (const float*)d_in[3];
    const float* Wk      = (const float*)d_in[4];
    const float* bk      = (const float*)d_in[5];
    const float* Wv      = (const float*)d_in[6];
    const float* bv      = (const float*)d_in[7];
    const float* gamma   = (const float*)d_in[8];
    const float* beta    = (const float*)d_in[9];
    const int*   topk    = (n_in > 10) ? (const int*)d_in[10] : nullptr;

    float* out  = (float*)d_out;                              // [B,S,N,H] fp32
    float* attn = out + (size_t)Bb * Ss * Nn * Hh;            // [B*N,S,S] fp32

    size_t smem = (size_t)(4 * 128 * XSTR + 128 * SSTR + 576) * sizeof(float); // 203008 B
    cudaFuncSetAttribute(fused_align_k, cudaFuncAttributeMaxDynamicSharedMemorySize, (int)smem);

    precompute_k<<<16, 256>>>(Wq, bq, Wk, bk);
    fused_align_k<<<Mm, NTH, smem>>>(traffic, text, Wv, bv, gamma, beta, topk, out, attn);
}

// round 2
// speedup vs baseline: 1.9245x; 1.9245x over previous
#include <cuda_runtime.h>
#include <math.h>

// Problem constants (fixed by setup_inputs)
#define Bb 4
#define Ss 128
#define Nn 512
#define Hh 64
#define Mm (Bb*Nn)          // 2048 heads
#define XSTR 65             // padded row stride (conflict-free lane-strided reads)
#define NTH 512

// Precomputed fused-projection operands
__device__ float g_G[Hh*Hh];   // scale * Wq^T Wk   [h1][h2]
__device__ float g_u[Hh];      // scale * Wq^T bk
__device__ float g_w[Hh];      // scale * Wk^T bq
__device__ float g_c0;         // scale * bq.bk

__global__ void precompute_k(const float* __restrict__ Wq, const float* __restrict__ bq,
                             const float* __restrict__ Wk, const float* __restrict__ bk) {
    int gid = blockIdx.x * blockDim.x + threadIdx.x;
    const float scale = 0.125f;  // 1/sqrt(64)
    if (gid < Hh * Hh) {
        int h1 = gid >> 6, h2 = gid & 63;
        float s = 0.f;
        #pragma unroll 8
        for (int o = 0; o < Hh; o++) s += Wq[o*Hh + h1] * Wk[o*Hh + h2];
        g_G[gid] = s * scale;
    }
    if (gid < Hh) {
        float s = 0.f, t = 0.f;
        #pragma unroll 8
        for (int o = 0; o < Hh; o++) { s += Wq[o*Hh + gid] * bk[o]; t += Wk[o*Hh + gid] * bq[o]; }
        g_u[gid] = s * scale;
        g_w[gid] = t * scale;
    }
    if (gid == 0) {
        float s = 0.f;
        for (int o = 0; o < Hh; o++) s += bq[o] * bk[o];
        g_c0 = s * scale;
    }
}

// monotonic key: max over keys == max over floats; full 32-bit (bit-exact selection)
__device__ __forceinline__ unsigned f2mono(float v) {
    unsigned u = __float_as_uint(v);
    return (u & 0x80000000u) ? ~u : (u | 0x80000000u);
}
__device__ __forceinline__ float mono2f(unsigned k) {
    unsigned u = (k & 0x80000000u) ? (k ^ 0x80000000u) : ~k;
    return __uint_as_float(u);
}

// One CTA per head m. 16 warps. Scores live in registers (8 rows per warp).
extern __shared__ float smf[];
__global__ void __launch_bounds__(NTH, 1)
fused_align_k(const float* __restrict__ traffic, const float* __restrict__ text,
              const float* __restrict__ Wv, const float* __restrict__ bv,
              const float* __restrict__ gamma, const float* __restrict__ beta,
              const int* __restrict__ topk_p,
              float* __restrict__ out_main, float* __restrict__ out_attn) {
    // shared layout (floats)
    float* xt_tr = smf;                 // 128*XSTR = 8320
    float* xt_tx = xt_tr + 128*XSTR;    // 8320
    float* Pm    = xt_tx + 128*XSTR;    // 8320
    float* vsm   = Pm    + 128*XSTR;    // 8320
    float* Gs    = vsm   + 128*XSTR;    // 4096
    float* Wvt   = Gs + 4096;           // 4096  [h][c]
    float* tail  = Wvt + 4096;
    float* sg  = tail;        // 64
    float* sb  = tail + 64;
    float* sbv = tail + 128;
    float* su  = tail + 192;
    float* sw_ = tail + 256;
    float* rb  = tail + 320;  // 128
    float* cb  = tail + 448;  // 128

    const int tid = threadIdx.x;
    const int lane = tid & 31;
    const int wrp = tid >> 5;          // 0..15
    const int m = blockIdx.x;
    const int b = m >> 9;
    const int n = m & (Nn - 1);

    const float* tr_base = traffic + ((size_t)b * Ss * Nn + n) * Hh;
    const float* tx_base = text    + ((size_t)b * Ss * Nn + n) * Hh;

    // ---- Stage 0: fill shared memory ----
    for (int i = tid; i < 4096; i += NTH) Gs[i] = g_G[i];
    for (int i = tid; i < 4096; i += NTH) {   // Wvt[h*64+c] = Wv[c*64+h]
        int c = i & 63, h = i >> 6;
        Wvt[i] = Wv[c * 64 + h];
    }
    for (int i = tid; i < 128 * 16; i += NTH) {
        int r = i >> 4, f = i & 15;
        float4 a = *(const float4*)(tr_base + (size_t)r * Nn * Hh + f * 4);
        float* d = xt_tr + r * XSTR + f * 4;
        d[0] = a.x; d[1] = a.y; d[2] = a.z; d[3] = a.w;
        float4 bx = *(const float4*)(tx_base + (size_t)r * Nn * Hh + f * 4);
        float* e = xt_tx + r * XSTR + f * 4;
        e[0] = bx.x; e[1] = bx.y; e[2] = bx.z; e[3] = bx.w;
    }
    if (tid < 64) {
        sg[tid] = gamma[tid]; sb[tid] = beta[tid]; sbv[tid] = bv[tid];
        su[tid] = g_u[tid];   sw_[tid] = g_w[tid];
    }
    __syncthreads();

    // ---- Stage 1: bias terms + P GEMM + V GEMM ----
    if (tid < 128) {
        float s = g_c0;
        const float* xr = xt_tr + tid * XSTR;
        #pragma unroll 8
        for (int h = 0; h < 64; h++) s += xr[h] * su[h];
        rb[tid] = s;
    } else if (tid < 256) {
        int t2 = tid - 128;
        float s = 0.f;
        const float* xr = xt_tx + t2 * XSTR;
        #pragma unroll 8
        for (int h = 0; h < 64; h++) s += xr[h] * sw_[h];
        cb[t2] = s;
    }

    {
        const int c0 = wrp * 4;          // 16 warps x 4 cols = 64
        float accP[4][4], accV[4][4];
        #pragma unroll
        for (int i = 0; i < 4; i++)
            #pragma unroll
            for (int j = 0; j < 4; j++) { accP[i][j] = 0.f; accV[i][j] = sbv[c0 + j]; }
        #pragma unroll 4
        for (int h = 0; h < 64; h++) {
            float xtr[4], xtx[4];
            #pragma unroll
            for (int i = 0; i < 4; i++) {
                xtr[i] = xt_tr[(lane + 32*i) * XSTR + h];   // conflict-free
                xtx[i] = xt_tx[(lane + 32*i) * XSTR + h];
            }
            #pragma unroll
            for (int j = 0; j < 4; j++) {
                float gv = Gs[h * 64 + c0 + j];             // broadcast
                float wv = Wvt[h * 64 + c0 + j];
                #pragma unroll
                for (int i = 0; i < 4; i++) {
                    accP[i][j] += xtr[i] * gv;
                    accV[i][j] += xtx[i] * wv;
                }
            }
        }
        #pragma unroll
        for (int i = 0; i < 4; i++)
            #pragma unroll
            for (int j = 0; j < 4; j++) {
                Pm [(lane + 32*i) * XSTR + c0 + j] = accP[i][j];
                vsm[(lane + 32*i) * XSTR + c0 + j] = accV[i][j];
            }
    }
    __syncthreads();

    // ---- Stage 2: scores GEMM into REGISTERS. Warp owns rows [8w, 8w+8).
    //      Lane owns columns t = lane + 32*tj, tj = 0..3. ----
    const int r0 = wrp * 8;
    float acc[8][4];
    {
        float cbl[4];
        #pragma unroll
        for (int tj = 0; tj < 4; tj++) cbl[tj] = cb[lane + 32*tj];
        #pragma unroll
        for (int ri = 0; ri < 8; ri++) {
            float r = rb[r0 + ri];
            #pragma unroll
            for (int tj = 0; tj < 4; tj++) acc[ri][tj] = r + cbl[tj];
        }
        #pragma unroll 2
        for (int h = 0; h < 64; h++) {
            float xb[4];
            #pragma unroll
            for (int tj = 0; tj < 4; tj++)
                xb[tj] = xt_tx[(lane + 32*tj) * XSTR + h];  // conflict-free
            #pragma unroll
            for (int ri = 0; ri < 8; ri++) {
                float pv = Pm[(r0 + ri) * XSTR + h];        // broadcast
                #pragma unroll
                for (int tj = 0; tj < 4; tj++) acc[ri][tj] += pv * xb[tj];
            }
        }
    }
    // no sync needed: scores are per-warp registers; vsm/xt_tr are stable

    // ---- Stage 3: per-row top-k (REDUX) + softmax + attn + sparse AV + LN ----
    int kk = 16;
    if (topk_p) { kk = topk_p[0]; if (kk < 1) kk = 1; if (kk > 32) kk = 32; }

    float* attn_base = out_attn + (size_t)m * Ss * Ss;
    const unsigned FULL = 0xffffffffu;

    for (int ri = 0; ri < 8; ++ri) {
        const int s = r0 + ri;
        float o0 = acc[ri][0], o1 = acc[ri][1], o2 = acc[ri][2], o3 = acc[ri][3];
        unsigned k0 = f2mono(o0), k1 = f2mono(o1), k2 = f2mono(o2), k3 = f2mono(o3);
        unsigned l0 = k0, l1 = k1, l2 = k2, l3 = k3;   // live copies (0 = cleared)
        unsigned maxk = 0, thrk = 0, selk = 0; int seli = 0;

        for (int it = 0; it < kk; ++it) {
            unsigned lb = l0; int slot = 0;
            if (l1 > lb) { lb = l1; slot = 1; }
            if (l2 > lb) { lb = l2; slot = 2; }
            if (l3 > lb) { lb = l3; slot = 3; }
            unsigned mw = __reduce_max_sync(FULL, lb);
            unsigned cand = (lb == mw) ? (unsigned)(slot * 32 + lane) : 0xffffffffu;
            unsigned tsel = __reduce_min_sync(FULL, cand);   // lowest index wins ties
            if (it == 0) maxk = mw;
            thrk = mw;
            if (lane == (int)(tsel & 31)) {
                int js = tsel >> 5;
                if (js == 0) l0 = 0; else if (js == 1) l1 = 0;
                else if (js == 2) l2 = 0; else l3 = 0;
            }
            if (lane == it) { selk = mw; seli = (int)tsel; }
        }

        float maxv = mono2f(maxk);
        float e0 = (k0 >= thrk) ? __expf(o0 - maxv) : 0.f;
        float e1 = (k1 >= thrk) ? __expf(o1 - maxv) : 0.f;
        float e2 = (k2 >= thrk) ? __expf(o2 - maxv) : 0.f;
        float e3 = (k3 >= thrk) ? __expf(o3 - maxv) : 0.f;
        float z = e0 + e1 + e2 + e3;
        #pragma unroll
        for (int off = 16; off > 0; off >>= 1) z += __shfl_xor_sync(FULL, z, off);
        float inv = 1.0f / z;

        float* ab = attn_base + (size_t)s * Ss;
        ab[lane]      = e0 * inv;
        ab[lane + 32] = e1 * inv;
        ab[lane + 64] = e2 * inv;
        ab[lane + 96] = e3 * inv;

        // sparse AV: lanes 0..kk-1 carry (p_i, idx_i)
        float p = (lane < kk) ? __expf(mono2f(selk) - maxv) * inv : 0.f;
        float a0 = 0.f, a1 = 0.f;
        for (int i2 = 0; i2 < kk; i2++) {
            float pi = __shfl_sync(FULL, p, i2);
            int   ti = __shfl_sync(FULL, seli, i2);
            const float* vr = vsm + ti * XSTR;
            a0 += pi * vr[lane];
            a1 += pi * vr[lane + 32];
        }

        // residual + LayerNorm over H=64 (2 elems/lane)
        float rr0 = a0 + xt_tr[s * XSTR + lane];
        float rr1 = a1 + xt_tr[s * XSTR + lane + 32];
        float sm1 = rr0 + rr1;
        #pragma unroll
        for (int off = 16; off > 0; off >>= 1) sm1 += __shfl_xor_sync(FULL, sm1, off);
        float mu = sm1 * (1.0f / 64.0f);
        float d0 = rr0 - mu, d1 = rr1 - mu;
        float sq = d0 * d0 + d1 * d1;
        #pragma unroll
        for (int off = 16; off > 0; off >>= 1) sq += __shfl_xor_sync(FULL, sq, off);
        float inv_sd = rsqrtf(sq * (1.0f / 64.0f) + 1e-5f);

        float* ob = out_main + (((size_t)(b * Ss + s)) * Nn + n) * Hh;
        ob[lane]      = d0 * inv_sd * sg[lane]      + sb[lane];
        ob[lane + 32] = d1 * inv_sd * sg[lane + 32] + sb[lane + 32];
    }
}

extern "C" void kernel_launch(void* const* d_in, const int* in_sizes, int n_in,
                              void* d_out, int out_size) {
    const float* traffic = (const float*)d_in[0];
    const float* text    = (const float*)d_in[1];
    const float* Wq      = (const float*)d_in[2];
    const float* bq      = (const float*)d_in[3];
    const float* Wk      = (const float*)d_in[4];
    const float* bk      = (const float*)d_in[5];
    const float* Wv      = (const float*)d_in[6];
    const float* bv      = (const float*)d_in[7];
    const float* gamma   = (const float*)d_in[8];
    const float* beta    = (const float*)d_in[9];
    const int*   topk    = (n_in > 10) ? (const int*)d_in[10] : nullptr;

    float* out  = (float*)d_out;                      // [B,S,N,H]
    float* attn = out + (size_t)Bb * Ss * Nn * Hh;    // [B*N,S,S]

    size_t smem = (size_t)(4 * 128 * XSTR + 4096 + 4096 + 576) * sizeof(float); // ~169.5 KB
    cudaFuncSetAttribute(fused_align_k, cudaFuncAttributeMaxDynamicSharedMemorySize, (int)smem);

    precompute_k<<<16, 256>>>(Wq, bq, Wk, bk);
    fused_align_k<<<Mm, NTH, smem>>>(traffic, text, Wv, bv, gamma, beta, topk, out, attn);
}

// round 3
// speedup vs baseline: 2.2023x; 1.1444x over previous
#include <cuda_runtime.h>
#include <math.h>

// Problem constants (fixed by setup_inputs)
#define Bb 4
#define Ss 128
#define Nn 512
#define Hh 64
#define Mm (Bb*Nn)          // 2048 heads
#define XSTR 68             // stride ≡ 4 (mod 32): float4 lane-strided access hits all 32 banks
#define NTH 1024

// Precomputed fused-projection operands
__device__ float g_Gt[Hh*Hh];  // TRANSPOSED: g_Gt[h2*64+h1] = scale * sum_o Wq[o][h1] Wk[o][h2]
__device__ float g_u[Hh];      // scale * Wq^T bk
__device__ float g_w[Hh];      // scale * Wk^T bq
__device__ float g_c0;         // scale * bq.bk

__global__ void precompute_k(const float* __restrict__ Wq, const float* __restrict__ bq,
                             const float* __restrict__ Wk, const float* __restrict__ bk) {
    int gid = blockIdx.x * blockDim.x + threadIdx.x;
    const float scale = 0.125f;  // 1/sqrt(64)
    if (gid < Hh * Hh) {
        int h2 = gid >> 6, h1 = gid & 63;   // output layout [h2][h1]
        float s = 0.f;
        #pragma unroll 8
        for (int o = 0; o < Hh; o++) s += Wq[o*Hh + h1] * Wk[o*Hh + h2];
        g_Gt[gid] = s * scale;
    }
    if (gid < Hh) {
        float s = 0.f, t = 0.f;
        #pragma unroll 8
        for (int o = 0; o < Hh; o++) { s += Wq[o*Hh + gid] * bk[o]; t += Wk[o*Hh + gid] * bq[o]; }
        g_u[gid] = s * scale;
        g_w[gid] = t * scale;
    }
    if (gid == 0) {
        float s = 0.f;
        for (int o = 0; o < Hh; o++) s += bq[o] * bk[o];
        g_c0 = s * scale;
    }
}

// monotonic key: max over keys == max over floats (bit-exact selection)
__device__ __forceinline__ unsigned f2mono(float v) {
    unsigned u = __float_as_uint(v);
    return (u & 0x80000000u) ? ~u : (u | 0x80000000u);
}
__device__ __forceinline__ float mono2f(unsigned k) {
    unsigned u = (k & 0x80000000u) ? (k ^ 0x80000000u) : ~k;
    return __uint_as_float(u);
}

__device__ __forceinline__ float4 lds4(const float* p) { return *(const float4*)p; }

// One CTA per head m. 32 warps. Scores in registers (4 rows per warp).
extern __shared__ float smf[];
__global__ void __launch_bounds__(NTH, 1)
fused_align_k(const float* __restrict__ traffic, const float* __restrict__ text,
              const float* __restrict__ Wv, const float* __restrict__ bv,
              const float* __restrict__ gamma, const float* __restrict__ beta,
              const int* __restrict__ topk_p,
              float* __restrict__ out_main, float* __restrict__ out_attn) {
    // shared layout (floats)
    float* xt_tr = smf;                 // 128*XSTR
    float* xt_tx = xt_tr + 128*XSTR;
    float* Pm    = xt_tx + 128*XSTR;
    float* vsm   = Pm    + 128*XSTR;
    float* Gs    = vsm   + 128*XSTR;    // 4096, layout [c][h] (c=h2 out col, h inner)
    float* Wvs   = Gs + 4096;           // 4096, layout [c][h] (== Wv row-major as-is)
    float* tail  = Wvs + 4096;
    float* sg  = tail;        // 64
    float* sb  = tail + 64;
    float* sbv = tail + 128;
    float* su  = tail + 192;
    float* sw_ = tail + 256;
    float* rb  = tail + 320;  // 128
    float* cb  = tail + 448;  // 128

    const int tid = threadIdx.x;
    const int lane = tid & 31;
    const int wrp = tid >> 5;          // 0..31
    const int m = blockIdx.x;
    const int b = m >> 9;
    const int n = m & (Nn - 1);

    const float* tr_base = traffic + ((size_t)b * Ss * Nn + n) * Hh;
    const float* tx_base = text    + ((size_t)b * Ss * Nn + n) * Hh;

    // ---- Stage 0: fill shared memory ----
    for (int i = tid; i < 4096; i += NTH) Gs[i]  = g_Gt[i];   // flat copy (pre-transposed)
    for (int i = tid; i < 4096; i += NTH) Wvs[i] = Wv[i];     // [c][h] already
    for (int i = tid; i < 128 * 16; i += NTH) {
        int r = i >> 4, f = i & 15;
        float4 a = *(const float4*)(tr_base + (size_t)r * Nn * Hh + f * 4);
        *(float4*)(xt_tr + r * XSTR + f * 4) = a;
        float4 bx = *(const float4*)(tx_base + (size_t)r * Nn * Hh + f * 4);
        *(float4*)(xt_tx + r * XSTR + f * 4) = bx;
    }
    if (tid < 64) {
        sg[tid] = gamma[tid]; sb[tid] = beta[tid]; sbv[tid] = bv[tid];
        su[tid] = g_u[tid];   sw_[tid] = g_w[tid];
    }
    __syncthreads();

    // ---- Stage 1: bias terms (first 256 threads) + P GEMM (warps 0-15) + V GEMM (warps 16-31) ----
    if (tid < 128) {
        float s = g_c0;
        const float* xr = xt_tr + tid * XSTR;
        #pragma unroll
        for (int h4 = 0; h4 < 64; h4 += 4) {
            float4 x = lds4(xr + h4), uu = lds4(su + h4);
            s += x.x*uu.x + x.y*uu.y + x.z*uu.z + x.w*uu.w;
        }
        rb[tid] = s;
    } else if (tid < 256) {
        int t2 = tid - 128;
        float s = 0.f;
        const float* xr = xt_tx + t2 * XSTR;
        #pragma unroll
        for (int h4 = 0; h4 < 64; h4 += 4) {
            float4 x = lds4(xr + h4), ww = lds4(sw_ + h4);
            s += x.x*ww.x + x.y*ww.y + x.z*ww.z + x.w*ww.w;
        }
        cb[t2] = s;
    }

    {
        const bool doP = (wrp < 16);
        const int c0 = (doP ? wrp : wrp - 16) * 4;        // 4 output cols
        const float* X = doP ? xt_tr : xt_tx;             // input tile
        const float* W = doP ? Gs : Wvs;                  // weights [c][h]
        float acc[4][4];
        #pragma unroll
        for (int i = 0; i < 4; i++)
            #pragma unroll
            for (int j = 0; j < 4; j++) acc[i][j] = doP ? 0.f : sbv[c0 + j];
        #pragma unroll
        for (int h4 = 0; h4 < 64; h4 += 4) {
            float4 x[4];
            #pragma unroll
            for (int i = 0; i < 4; i++)
                x[i] = lds4(X + (lane + 32*i) * XSTR + h4);   // conflict-free float4
            #pragma unroll
            for (int j = 0; j < 4; j++) {
                float4 w = lds4(W + (c0 + j) * 64 + h4);      // broadcast float4
                #pragma unroll
                for (int i = 0; i < 4; i++)
                    acc[i][j] += x[i].x*w.x + x[i].y*w.y + x[i].z*w.z + x[i].w*w.w;
            }
        }
        float* D = doP ? Pm : vsm;
        #pragma unroll
        for (int i = 0; i < 4; i++) {
            float4 o; o.x = acc[i][0]; o.y = acc[i][1]; o.z = acc[i][2]; o.w = acc[i][3];
            *(float4*)(D + (lane + 32*i) * XSTR + c0) = o;    // conflict-free STS.128
        }
    }
    __syncthreads();

    // ---- Stage 2: scores GEMM into registers. Warp owns rows [4w, 4w+4).
    //      Lane owns cols t = lane + 32*tj, tj = 0..3. ----
    const int r0 = wrp * 4;
    float acc[4][4];
    {
        float cbl[4];
        #pragma unroll
        for (int tj = 0; tj < 4; tj++) cbl[tj] = cb[lane + 32*tj];
        #pragma unroll
        for (int ri = 0; ri < 4; ri++) {
            float r = rb[r0 + ri];
            #pragma unroll
            for (int tj = 0; tj < 4; tj++) acc[ri][tj] = r + cbl[tj];
        }
        #pragma unroll
        for (int h4 = 0; h4 < 64; h4 += 4) {
            float4 xb[4];
            #pragma unroll
            for (int tj = 0; tj < 4; tj++)
                xb[tj] = lds4(xt_tx + (lane + 32*tj) * XSTR + h4);  // conflict-free float4
            #pragma unroll
            for (int ri = 0; ri < 4; ri++) {
                float4 pv = lds4(Pm + (r0 + ri) * XSTR + h4);       // broadcast float4
                #pragma unroll
                for (int tj = 0; tj < 4; tj++)
                    acc[ri][tj] += pv.x*xb[tj].x + pv.y*xb[tj].y + pv.z*xb[tj].z + pv.w*xb[tj].w;
            }
        }
    }
    // scores are per-warp registers; vsm/xt_tr stable — no sync needed

    // ---- Stage 3: per-row top-k (REDUX) + softmax + attn + sparse AV + LN ----
    int kk = 16;
    if (topk_p) { kk = topk_p[0]; if (kk < 1) kk = 1; if (kk > 32) kk = 32; }

    float* attn_base = out_attn + (size_t)m * Ss * Ss;
    const unsigned FULL = 0xffffffffu;

    for (int ri = 0; ri < 4; ++ri) {
        const int s = r0 + ri;
        float o0 = acc[ri][0], o1 = acc[ri][1], o2 = acc[ri][2], o3 = acc[ri][3];
        unsigned k0 = f2mono(o0), k1 = f2mono(o1), k2 = f2mono(o2), k3 = f2mono(o3);
        unsigned l0 = k0, l1 = k1, l2 = k2, l3 = k3;   // live copies (0 = cleared)
        unsigned maxk = 0, thrk = 0, selk = 0; int seli = 0;

        for (int it = 0; it < kk; ++it) {
            unsigned lb = l0; int slot = 0;
            if (l1 > lb) { lb = l1; slot = 1; }
            if (l2 > lb) { lb = l2; slot = 2; }
            if (l3 > lb) { lb = l3; slot = 3; }
            unsigned mw = __reduce_max_sync(FULL, lb);
            unsigned cand = (lb == mw) ? (unsigned)(slot * 32 + lane) : 0xffffffffu;
            unsigned tsel = __reduce_min_sync(FULL, cand);   // lowest index wins ties
            if (it == 0) maxk = mw;
            thrk = mw;
            if (lane == (int)(tsel & 31)) {
                int js = tsel >> 5;
                if (js == 0) l0 = 0; else if (js == 1) l1 = 0;
                else if (js == 2) l2 = 0; else l3 = 0;
            }
            if (lane == it) { selk = mw; seli = (int)tsel; }
        }

        float maxv = mono2f(maxk);
        float e0 = (k0 >= thrk) ? __expf(o0 - maxv) : 0.f;
        float e1 = (k1 >= thrk) ? __expf(o1 - maxv) : 0.f;
        float e2 = (k2 >= thrk) ? __expf(o2 - maxv) : 0.f;
        float e3 = (k3 >= thrk) ? __expf(o3 - maxv) : 0.f;
        float z = e0 + e1 + e2 + e3;
        #pragma unroll
        for (int off = 16; off > 0; off >>= 1) z += __shfl_xor_sync(FULL, z, off);
        float inv = 1.0f / z;

        float* ab = attn_base + (size_t)s * Ss;
        ab[lane]      = e0 * inv;
        ab[lane + 32] = e1 * inv;
        ab[lane + 64] = e2 * inv;
        ab[lane + 96] = e3 * inv;

        // sparse AV: lanes 0..kk-1 carry (p_i, idx_i)
        float p = (lane < kk) ? __expf(mono2f(selk) - maxv) * inv : 0.f;
        float a0 = 0.f, a1 = 0.f;
        for (int i2 = 0; i2 < kk; i2++) {
            float pi = __shfl_sync(FULL, p, i2);
            int   ti = __shfl_sync(FULL, seli, i2);
            const float* vr = vsm + ti * XSTR;
            a0 += pi * vr[lane];
            a1 += pi * vr[lane + 32];
        }

        // residual + LayerNorm over H=64 (2 elems/lane)
        float rr0 = a0 + xt_tr[s * XSTR + lane];
        float rr1 = a1 + xt_tr[s * XSTR + lane + 32];
        float sm1 = rr0 + rr1;
        #pragma unroll
        for (int off = 16; off > 0; off >>= 1) sm1 += __shfl_xor_sync(FULL, sm1, off);
        float mu = sm1 * (1.0f / 64.0f);
        float d0 = rr0 - mu, d1 = rr1 - mu;
        float sq = d0 * d0 + d1 * d1;
        #pragma unroll
        for (int off = 16; off > 0; off >>= 1) sq += __shfl_xor_sync(FULL, sq, off);
        float inv_sd = rsqrtf(sq * (1.0f / 64.0f) + 1e-5f);

        float* ob = out_main + (((size_t)(b * Ss + s)) * Nn + n) * Hh;
        ob[lane]      = d0 * inv_sd * sg[lane]      + sb[lane];
        ob[lane + 32] = d1 * inv_sd * sg[lane + 32] + sb[lane + 32];
    }
}

extern "C" void kernel_launch(void* const* d_in, const int* in_sizes, int n_in,
                              void* d_out, int out_size) {
    const float* traffic = (const float*)d_in[0];
    const float* text    = (const float*)d_in[1];
    const float* Wq      = (const float*)d_in[2];
    const float* bq      = (const float*)d_in[3];
    const float* Wk      = (const float*)d_in[4];
    const float* bk      = (const float*)d_in[5];
    const float* Wv      = (const float*)d_in[6];
    const float* bv      = (const float*)d_in[7];
    const float* gamma   = (const float*)d_in[8];
    const float* beta    = (const float*)d_in[9];
    const int*   topk    = (n_in > 10) ? (const int*)d_in[10] : nullptr;

    float* out  = (float*)d_out;                      // [B,S,N,H]
    float* attn = out + (size_t)Bb * Ss * Nn * Hh;    // [B*N,S,S]

    size_t smem = (size_t)(4 * 128 * XSTR + 4096 + 4096 + 576) * sizeof(float); // ~174 KB
    cudaFuncSetAttribute(fused_align_k, cudaFuncAttributeMaxDynamicSharedMemorySize, (int)smem);

    precompute_k<<<16, 256>>>(Wq, bq, Wk, bk);
    fused_align_k<<<Mm, NTH, smem>>>(traffic, text, Wv, bv, gamma, beta, topk, out, attn);
}